// round 14
// baseline (speedup 1.0000x reference)
#include <cuda_runtime.h>
#include <cuda_bf16.h>
#include <cuda_fp16.h>
#include <cstdint>

#define DEVINL __device__ __forceinline__

// ---------------- problem constants ----------------
constexpr int F  = 128;      // feature dim (K)
constexpr int B  = 256;      // batch
constexpr int R  = 512;      // J*B GEMM rows
constexpr int Q  = 65536;    // queue size
constexpr int TN = 64;       // queue rows per chunk
constexpr int QG = Q / TN;   // 1024 chunks
constexpr int SLOTS = 148;   // persistent CTAs (1 per SM)
constexpr int SSTR = 272;    // padded bf16 row stride in smem bytes
constexpr float INV_T = 10.0f;
constexpr float LOG2E = 1.4426950408889634f;
constexpr float CEXP  = INV_T * LOG2E;   // exp(10*d) = 2^(CEXP*d); folded into A

constexpr int F32_BUF  = TN * F * 4;     // 32768 raw fp32 chunk
constexpr int BF_BUF   = TN * SSTR;      // 17408 padded bf16 tile
constexpr int SMEM_BYTES = 2 * F32_BUF + 2 * BF_BUF;   // 100352

// ---------------- scratch (no allocs allowed) ----------------
__device__ float g_sq[R * SLOTS];        // [row][slot] partials
__device__ float g_pos[R];
__device__ float g_sqrow[R];

// ---------------- helpers ----------------
DEVINL float ex2f(float x) { float y; asm("ex2.approx.ftz.f32 %0, %1;" : "=f"(y) : "f"(x)); return y; }

DEVINL uint32_t cvt2(float a, float b) {
    __nv_bfloat162 h = __floats2bfloat162_rn(a, b);
    return *reinterpret_cast<uint32_t*>(&h);
}

DEVINL uint32_t smem_u32(const void* p) {
    uint32_t a;
    asm("{ .reg .u64 t; cvta.to.shared.u64 t, %1; cvt.u32.u64 %0, t; }" : "=r"(a) : "l"(p));
    return a;
}

DEVINL void mma16816(float* d, const uint32_t* a, uint32_t b0, uint32_t b1) {
    asm volatile(
        "mma.sync.aligned.m16n8k16.row.col.f32.bf16.bf16.f32 "
        "{%0,%1,%2,%3}, {%4,%5,%6,%7}, {%8,%9}, {%0,%1,%2,%3};"
        : "+f"(d[0]), "+f"(d[1]), "+f"(d[2]), "+f"(d[3])
        : "r"(a[0]), "r"(a[1]), "r"(a[2]), "r"(a[3]), "r"(b0), "r"(b1));
}

DEVINL void ldsm_x4(uint32_t* r, uint32_t addr) {
    asm volatile("ldmatrix.sync.aligned.m8n8.x4.shared.b16 {%0,%1,%2,%3}, [%4];"
                 : "=r"(r[0]), "=r"(r[1]), "=r"(r[2]), "=r"(r[3]) : "r"(addr));
}

DEVINL void cp16(uint32_t smem_dst, const void* gsrc) {
    asm volatile("cp.async.cg.shared.global [%0], [%1], 16;" :: "r"(smem_dst), "l"(gsrc));
}
DEVINL void cp_commit() { asm volatile("cp.async.commit_group;" ::: "memory"); }
DEVINL void cp_wait1()  { asm volatile("cp.async.wait_group 1;" ::: "memory"); }

// paired exp2 via one MUFU op: returns f.x+f.y contribution terms
DEVINL void exp2pair(float& s, float a, float b) {
    half2 e = h2exp2(__floats2half2_rn(a, b));   // ex2.approx.f16x2 (one MUFU issue)
    float2 f = __half22float2(e);
    s += f.x + f.y;
}

// ================= kernel 1: persistent HMMA GEMM (R11 mainloop, f16x2 exp epilogue) =================
__global__ void __launch_bounds__(512, 1)
gemm_exp_kernel(const float* __restrict__ V, const float* __restrict__ queue) {
    extern __shared__ char smem[];
    const uint32_t sb   = smem_u32(smem);
    const uint32_t bf_b = sb + 2 * F32_BUF;

    const int tid  = threadIdx.x;                // 0..511
    const int w    = tid >> 5;                   // 0..15 -> rows w*32..+31
    const int lane = tid & 31;
    const int g    = lane >> 2;
    const int tg   = lane & 3;
    const int slot = blockIdx.x;                 // 0..147

    // ---- A fragments: fp32 V -> bf16 regs, pre-scaled by CEXP (64 regs) ----
    uint32_t a[2][8][4];
    {
        const float* Ab = V + (size_t)(w * 32) * F;
#pragma unroll
        for (int m = 0; m < 2; m++)
#pragma unroll
            for (int k = 0; k < 8; k++) {
                int r0 = m * 16 + g, r1 = r0 + 8;
                int c0 = k * 16 + 2 * tg, c1 = c0 + 8;
                float2 f;
                f = *(const float2*)(Ab + r0 * F + c0); a[m][k][0] = cvt2(f.x * CEXP, f.y * CEXP);
                f = *(const float2*)(Ab + r1 * F + c0); a[m][k][1] = cvt2(f.x * CEXP, f.y * CEXP);
                f = *(const float2*)(Ab + r0 * F + c1); a[m][k][2] = cvt2(f.x * CEXP, f.y * CEXP);
                f = *(const float2*)(Ab + r1 * F + c1); a[m][k][3] = cvt2(f.x * CEXP, f.y * CEXP);
            }
    }

    // fp32 staging: 64 rows x 512B; each thread 4 x 16B
    const int srow = tid >> 3;
    const int sseg = (tid & 7) * 64;
    auto stage = [&](int buf, int qg) {
        const char* src = (const char*)(queue + (size_t)qg * TN * F) + srow * 512 + sseg;
        uint32_t dst = sb + buf * F32_BUF + srow * 512 + sseg;
#pragma unroll
        for (int j = 0; j < 4; j++) cp16(dst + j * 16, src + j * 16);
    };

    // convert one quarter (512 float4) of fp32 buf -> padded bf16 tile
    auto convert_q = [&](int buf, int quarter) {
        int idx = quarter * 512 + tid;           // 0..2047
        int row = idx >> 5, c4 = idx & 31;
        float4 v4 = *((const float4*)(smem + buf * F32_BUF) + idx);
        uint2 o; o.x = cvt2(v4.x, v4.y); o.y = cvt2(v4.z, v4.w);
        *reinterpret_cast<uint2*>(smem + 2 * F32_BUF + buf * BF_BUF + row * SSTR + c4 * 8) = o;
    };

    const int nch = (QG - slot + SLOTS - 1) / SLOTS;   // 6 or 7

    float s00 = 0.f, s01 = 0.f, s10 = 0.f, s11 = 0.f;

    stage(0, slot); cp_commit();
    stage(1, slot + SLOTS); cp_commit();
    cp_wait1();                    // stage(0) done
#pragma unroll
    for (int q = 0; q < 4; q++) convert_q(0, q);
    __syncthreads();

    int qg = slot;
#pragma unroll 1
    for (int c = 0; c < nch; c++, qg += SLOTS) {
        if (c + 2 < nch) stage(c & 1, qg + 2 * SLOTS);   // fp32 buf (c+2)&1 == c&1
        cp_commit();                                      // uniform group count

        const uint32_t lbase = bf_b + (c & 1) * BF_BUF + (lane & 7) * SSTR + (lane >> 3) * 16;
        const bool has_next = (c + 1 < nch);

        // software pipeline: bqp = kp0,kp1 fragments (prefetched); bqc = kp2,kp3 (in-iter)
        uint32_t bqp[8], bqc[8];
        ldsm_x4(bqp,     lbase);
        ldsm_x4(bqp + 4, lbase + 64);

        float u[8];
#pragma unroll
        for (int n8 = 0; n8 < 8; n8++) {
            if (n8 == 4) cp_wait1();                      // stage(c+1) landed
            if (n8 >= 4 && has_next) convert_q((c + 1) & 1, n8 - 4);

            const uint32_t nb  = lbase + n8 * 8 * SSTR;
            const uint32_t nbn = lbase + ((n8 + 1) & 7) * 8 * SSTR;

            ldsm_x4(bqc,     nb + 128);
            ldsm_x4(bqc + 4, nb + 192);

            float x0[4] = {0,0,0,0}, x1[4] = {0,0,0,0};
            float y0[4] = {0,0,0,0}, y1[4] = {0,0,0,0};
            mma16816(x0, a[0][0], bqp[0], bqp[1]);
            mma16816(x0, a[0][1], bqp[2], bqp[3]);
            mma16816(y0, a[1][0], bqp[0], bqp[1]);
            mma16816(y0, a[1][1], bqp[2], bqp[3]);
            mma16816(x1, a[0][2], bqp[4], bqp[5]);
            mma16816(x1, a[0][3], bqp[6], bqp[7]);
            mma16816(y1, a[1][2], bqp[4], bqp[5]);
            mma16816(y1, a[1][3], bqp[6], bqp[7]);
            if (n8 < 7) {
                ldsm_x4(bqp,     nbn);
                ldsm_x4(bqp + 4, nbn + 64);
            }
            mma16816(x0, a[0][4], bqc[0], bqc[1]);
            mma16816(x0, a[0][5], bqc[2], bqc[3]);
            mma16816(y0, a[1][4], bqc[0], bqc[1]);
            mma16816(y0, a[1][5], bqc[2], bqc[3]);
            mma16816(x1, a[0][6], bqc[4], bqc[5]);
            mma16816(x1, a[0][7], bqc[6], bqc[7]);
            mma16816(y1, a[1][6], bqc[4], bqc[5]);
            mma16816(y1, a[1][7], bqc[6], bqc[7]);

            if (n8 > 0) {   // deferred paired exp2 of previous iteration (half the MUFU ops)
                exp2pair(s00, u[0], u[1]);
                exp2pair(s01, u[2], u[3]);
                exp2pair(s10, u[4], u[5]);
                exp2pair(s11, u[6], u[7]);
            }
#pragma unroll
            for (int i = 0; i < 4; i++) { u[i] = x0[i] + x1[i]; u[4 + i] = y0[i] + y1[i]; }
        }
        exp2pair(s00, u[0], u[1]);
        exp2pair(s01, u[2], u[3]);
        exp2pair(s10, u[4], u[5]);
        exp2pair(s11, u[6], u[7]);

        __syncthreads();
    }

    // ---- quad reduce over tg, transposed deterministic store ----
    s00 += __shfl_xor_sync(0xFFFFFFFFu, s00, 1); s00 += __shfl_xor_sync(0xFFFFFFFFu, s00, 2);
    s01 += __shfl_xor_sync(0xFFFFFFFFu, s01, 1); s01 += __shfl_xor_sync(0xFFFFFFFFu, s01, 2);
    s10 += __shfl_xor_sync(0xFFFFFFFFu, s10, 1); s10 += __shfl_xor_sync(0xFFFFFFFFu, s10, 2);
    s11 += __shfl_xor_sync(0xFFFFFFFFu, s11, 1); s11 += __shfl_xor_sync(0xFFFFFFFFu, s11, 2);
    if (tg == 0) {
        int rb = w * 32;
        g_sq[(size_t)(rb + g)      * SLOTS + slot] = s00;
        g_sq[(size_t)(rb + g + 8)  * SLOTS + slot] = s01;
        g_sq[(size_t)(rb + g + 16) * SLOTS + slot] = s10;
        g_sq[(size_t)(rb + g + 24) * SLOTS + slot] = s11;
    }
}

// ================= kernel 2: per-row pos + slot reduction (64 CTAs, warp/row) =================
__global__ void __launch_bounds__(256) reduce_kernel(const float* __restrict__ V,
                                                     const float* __restrict__ L) {
    const int w    = threadIdx.x >> 5;
    const int lane = threadIdx.x & 31;
    const int row  = blockIdx.x * 8 + w;      // 64 CTAs x 8 warps = 512 rows

    float4 av = ((const float4*)(V + (size_t)row * F))[lane];
    float4 lv = ((const float4*)(L + (size_t)(row & (B - 1)) * F))[lane];
    float p = av.x * lv.x + av.y * lv.y + av.z * lv.z + av.w * lv.w;
#pragma unroll
    for (int o = 16; o > 0; o >>= 1) p += __shfl_xor_sync(0xFFFFFFFFu, p, o);

    const float* sr = g_sq + (size_t)row * SLOTS;
    float sq = 0.f;
#pragma unroll
    for (int i = lane; i < SLOTS; i += 32) sq += sr[i];
#pragma unroll
    for (int o = 16; o > 0; o >>= 1) sq += __shfl_xor_sync(0xFFFFFFFFu, sq, o);

    if (lane == 0) {
        g_pos[row]   = p * INV_T;
        g_sqrow[row] = sq;
    }
}

// ================= kernel 3: final loss (tiny) =================
__global__ void final_kernel(float* __restrict__ out) {
    __shared__ float sh[R];
    int t = threadIdx.x;          // 512
    float pos = g_pos[t];
    float sq  = g_sqrow[t];
    sh[t] = ex2f(pos * LOG2E);
    __syncthreads();
    for (int off = 128; off > 0; off >>= 1) {
        if ((t & 255) < off) sh[t] += sh[t + off];
        __syncthreads();
    }
    float spos = sh[(t >> 8) << 8];
    __syncthreads();
    sh[t] = pos - logf(spos + sq);
    __syncthreads();
    for (int off = 256; off > 0; off >>= 1) {
        if (t < off) sh[t] += sh[t + off];
        __syncthreads();
    }
    if (t == 0) out[0] = -sh[0] / (float)B;
}

// ================= launch =================
extern "C" void kernel_launch(void* const* d_in, const int* in_sizes, int n_in,
                              void* d_out, int out_size) {
    (void)in_sizes; (void)n_in; (void)out_size;
    const float* V     = (const float*)d_in[0];
    const float* L     = (const float*)d_in[1];
    const float* queue = (const float*)d_in[2];
    float* out = (float*)d_out;

    cudaFuncSetAttribute(gemm_exp_kernel, cudaFuncAttributeMaxDynamicSharedMemorySize, SMEM_BYTES);

    gemm_exp_kernel<<<SLOTS, 512, SMEM_BYTES>>>(V, queue);
    reduce_kernel<<<64, 256>>>(V, L);
    final_kernel<<<1, 512>>>(out);
}

// round 15
// speedup vs baseline: 1.1012x; 1.1012x over previous
#include <cuda_runtime.h>
#include <cuda_bf16.h>
#include <cstdint>

#define DEVINL __device__ __forceinline__

// ---------------- problem constants ----------------
constexpr int F  = 128;      // feature dim (K)
constexpr int B  = 256;      // batch
constexpr int R  = 512;      // J*B GEMM rows
constexpr int Q  = 65536;    // queue size
constexpr int TN = 64;       // queue rows per chunk
constexpr int QG = Q / TN;   // 1024 chunks
constexpr int SLOTS = 148;   // persistent CTAs (1 per SM)
constexpr int SSTR = 272;    // padded bf16 row stride in smem bytes
constexpr float INV_T = 10.0f;
constexpr float LOG2E = 1.4426950408889634f;
constexpr float CEXP  = INV_T * LOG2E;   // exp(10*d) = 2^(CEXP*d); folded into A

constexpr int F32_BUF  = TN * F * 4;     // 32768 raw fp32 chunk
constexpr int BF_BUF   = TN * SSTR;      // 17408 padded bf16 tile
constexpr int SMEM_BYTES = 2 * F32_BUF + 2 * BF_BUF;   // 100352

// ---------------- scratch (no allocs allowed) ----------------
__device__ float g_sq[R * SLOTS];        // [row][slot] partials
__device__ float g_pos[R];
__device__ float g_sqrow[R];

// ---------------- helpers ----------------
DEVINL float ex2f(float x) { float y; asm("ex2.approx.ftz.f32 %0, %1;" : "=f"(y) : "f"(x)); return y; }

DEVINL uint32_t cvt2(float a, float b) {
    __nv_bfloat162 h = __floats2bfloat162_rn(a, b);
    return *reinterpret_cast<uint32_t*>(&h);
}

DEVINL uint32_t smem_u32(const void* p) {
    uint32_t a;
    asm("{ .reg .u64 t; cvta.to.shared.u64 t, %1; cvt.u32.u64 %0, t; }" : "=r"(a) : "l"(p));
    return a;
}

DEVINL void mma16816(float* d, const uint32_t* a, uint32_t b0, uint32_t b1) {
    asm volatile(
        "mma.sync.aligned.m16n8k16.row.col.f32.bf16.bf16.f32 "
        "{%0,%1,%2,%3}, {%4,%5,%6,%7}, {%8,%9}, {%0,%1,%2,%3};"
        : "+f"(d[0]), "+f"(d[1]), "+f"(d[2]), "+f"(d[3])
        : "r"(a[0]), "r"(a[1]), "r"(a[2]), "r"(a[3]), "r"(b0), "r"(b1));
}

DEVINL void ldsm_x4(uint32_t* r, uint32_t addr) {
    asm volatile("ldmatrix.sync.aligned.m8n8.x4.shared.b16 {%0,%1,%2,%3}, [%4];"
                 : "=r"(r[0]), "=r"(r[1]), "=r"(r[2]), "=r"(r[3]) : "r"(addr));
}

DEVINL void cp16(uint32_t smem_dst, const void* gsrc) {
    asm volatile("cp.async.cg.shared.global [%0], [%1], 16;" :: "r"(smem_dst), "l"(gsrc));
}
DEVINL void cp_commit() { asm volatile("cp.async.commit_group;" ::: "memory"); }
DEVINL void cp_wait1()  { asm volatile("cp.async.wait_group 1;" ::: "memory"); }

// ================= kernel 1: persistent HMMA GEMM (R11 mainloop; convert moved early) =================
__global__ void __launch_bounds__(512, 1)
gemm_exp_kernel(const float* __restrict__ V, const float* __restrict__ queue) {
    extern __shared__ char smem[];
    const uint32_t sb   = smem_u32(smem);
    const uint32_t bf_b = sb + 2 * F32_BUF;

    const int tid  = threadIdx.x;                // 0..511
    const int w    = tid >> 5;                   // 0..15 -> rows w*32..+31
    const int lane = tid & 31;
    const int g    = lane >> 2;
    const int tg   = lane & 3;
    const int slot = blockIdx.x;                 // 0..147

    // ---- A fragments: fp32 V -> bf16 regs, pre-scaled by CEXP (64 regs) ----
    uint32_t a[2][8][4];
    {
        const float* Ab = V + (size_t)(w * 32) * F;
#pragma unroll
        for (int m = 0; m < 2; m++)
#pragma unroll
            for (int k = 0; k < 8; k++) {
                int r0 = m * 16 + g, r1 = r0 + 8;
                int c0 = k * 16 + 2 * tg, c1 = c0 + 8;
                float2 f;
                f = *(const float2*)(Ab + r0 * F + c0); a[m][k][0] = cvt2(f.x * CEXP, f.y * CEXP);
                f = *(const float2*)(Ab + r1 * F + c0); a[m][k][1] = cvt2(f.x * CEXP, f.y * CEXP);
                f = *(const float2*)(Ab + r0 * F + c1); a[m][k][2] = cvt2(f.x * CEXP, f.y * CEXP);
                f = *(const float2*)(Ab + r1 * F + c1); a[m][k][3] = cvt2(f.x * CEXP, f.y * CEXP);
            }
    }

    // fp32 staging: 64 rows x 512B; each thread 4 x 16B
    const int srow = tid >> 3;
    const int sseg = (tid & 7) * 64;
    auto stage = [&](int buf, int qg) {
        const char* src = (const char*)(queue + (size_t)qg * TN * F) + srow * 512 + sseg;
        uint32_t dst = sb + buf * F32_BUF + srow * 512 + sseg;
#pragma unroll
        for (int j = 0; j < 4; j++) cp16(dst + j * 16, src + j * 16);
    };

    // convert one quarter (512 float4) of fp32 buf -> padded bf16 tile
    auto convert_q = [&](int buf, int quarter) {
        int idx = quarter * 512 + tid;           // 0..2047
        int row = idx >> 5, c4 = idx & 31;
        float4 v4 = *((const float4*)(smem + buf * F32_BUF) + idx);
        uint2 o; o.x = cvt2(v4.x, v4.y); o.y = cvt2(v4.z, v4.w);
        *reinterpret_cast<uint2*>(smem + 2 * F32_BUF + buf * BF_BUF + row * SSTR + c4 * 8) = o;
    };

    const int nch = (QG - slot + SLOTS - 1) / SLOTS;   // 6 or 7

    float s00 = 0.f, s01 = 0.f, s10 = 0.f, s11 = 0.f;

    stage(0, slot); cp_commit();
    stage(1, slot + SLOTS); cp_commit();
    cp_wait1();                    // stage(0) done
#pragma unroll
    for (int q = 0; q < 4; q++) convert_q(0, q);
    __syncthreads();

    int qg = slot;
#pragma unroll 1
    for (int c = 0; c < nch; c++, qg += SLOTS) {
        if (c + 2 < nch) stage(c & 1, qg + 2 * SLOTS);   // fp32 buf (c+2)&1 == c&1
        cp_commit();                                      // uniform group count

        const uint32_t lbase = bf_b + (c & 1) * BF_BUF + (lane & 7) * SSTR + (lane >> 3) * 16;
        const bool has_next = (c + 1 < nch);

        // software pipeline: bqp = kp0,kp1 fragments (prefetched); bqc = kp2,kp3 (in-iter)
        uint32_t bqp[8], bqc[8];
        ldsm_x4(bqp,     lbase);
        ldsm_x4(bqp + 4, lbase + 64);

        float u[8];
#pragma unroll
        for (int n8 = 0; n8 < 8; n8++) {
            if (n8 == 0) cp_wait1();                      // stage(c+1) landed (issued 1 chunk ago)
            if (n8 < 4 && has_next) convert_q((c + 1) & 1, n8);   // converts done by mid-chunk

            const uint32_t nb  = lbase + n8 * 8 * SSTR;
            const uint32_t nbn = lbase + ((n8 + 1) & 7) * 8 * SSTR;

            ldsm_x4(bqc,     nb + 128);
            ldsm_x4(bqc + 4, nb + 192);

            float x0[4] = {0,0,0,0}, x1[4] = {0,0,0,0};
            float y0[4] = {0,0,0,0}, y1[4] = {0,0,0,0};
            mma16816(x0, a[0][0], bqp[0], bqp[1]);
            mma16816(x0, a[0][1], bqp[2], bqp[3]);
            mma16816(y0, a[1][0], bqp[0], bqp[1]);
            mma16816(y0, a[1][1], bqp[2], bqp[3]);
            mma16816(x1, a[0][2], bqp[4], bqp[5]);
            mma16816(x1, a[0][3], bqp[6], bqp[7]);
            mma16816(y1, a[1][2], bqp[4], bqp[5]);
            mma16816(y1, a[1][3], bqp[6], bqp[7]);
            if (n8 < 7) {
                ldsm_x4(bqp,     nbn);
                ldsm_x4(bqp + 4, nbn + 64);
            }
            mma16816(x0, a[0][4], bqc[0], bqc[1]);
            mma16816(x0, a[0][5], bqc[2], bqc[3]);
            mma16816(y0, a[1][4], bqc[0], bqc[1]);
            mma16816(y0, a[1][5], bqc[2], bqc[3]);
            mma16816(x1, a[0][6], bqc[4], bqc[5]);
            mma16816(x1, a[0][7], bqc[6], bqc[7]);
            mma16816(y1, a[1][6], bqc[4], bqc[5]);
            mma16816(y1, a[1][7], bqc[6], bqc[7]);

            if (n8 > 0) {   // deferred ex2 of previous iteration overlaps this iter's mma
                s00 += ex2f(u[0]) + ex2f(u[1]);
                s01 += ex2f(u[2]) + ex2f(u[3]);
                s10 += ex2f(u[4]) + ex2f(u[5]);
                s11 += ex2f(u[6]) + ex2f(u[7]);
            }
#pragma unroll
            for (int i = 0; i < 4; i++) { u[i] = x0[i] + x1[i]; u[4 + i] = y0[i] + y1[i]; }
        }
        s00 += ex2f(u[0]) + ex2f(u[1]);
        s01 += ex2f(u[2]) + ex2f(u[3]);
        s10 += ex2f(u[4]) + ex2f(u[5]);
        s11 += ex2f(u[6]) + ex2f(u[7]);

        __syncthreads();
    }

    // ---- quad reduce over tg, transposed deterministic store ----
    s00 += __shfl_xor_sync(0xFFFFFFFFu, s00, 1); s00 += __shfl_xor_sync(0xFFFFFFFFu, s00, 2);
    s01 += __shfl_xor_sync(0xFFFFFFFFu, s01, 1); s01 += __shfl_xor_sync(0xFFFFFFFFu, s01, 2);
    s10 += __shfl_xor_sync(0xFFFFFFFFu, s10, 1); s10 += __shfl_xor_sync(0xFFFFFFFFu, s10, 2);
    s11 += __shfl_xor_sync(0xFFFFFFFFu, s11, 1); s11 += __shfl_xor_sync(0xFFFFFFFFu, s11, 2);
    if (tg == 0) {
        int rb = w * 32;
        g_sq[(size_t)(rb + g)      * SLOTS + slot] = s00;
        g_sq[(size_t)(rb + g + 8)  * SLOTS + slot] = s01;
        g_sq[(size_t)(rb + g + 16) * SLOTS + slot] = s10;
        g_sq[(size_t)(rb + g + 24) * SLOTS + slot] = s11;
    }
}

// ================= kernel 2: per-row pos + slot reduction (64 CTAs, warp/row) =================
__global__ void __launch_bounds__(256) reduce_kernel(const float* __restrict__ V,
                                                     const float* __restrict__ L) {
    const int w    = threadIdx.x >> 5;
    const int lane = threadIdx.x & 31;
    const int row  = blockIdx.x * 8 + w;      // 64 CTAs x 8 warps = 512 rows

    float4 av = ((const float4*)(V + (size_t)row * F))[lane];
    float4 lv = ((const float4*)(L + (size_t)(row & (B - 1)) * F))[lane];
    float p = av.x * lv.x + av.y * lv.y + av.z * lv.z + av.w * lv.w;
#pragma unroll
    for (int o = 16; o > 0; o >>= 1) p += __shfl_xor_sync(0xFFFFFFFFu, p, o);

    const float* sr = g_sq + (size_t)row * SLOTS;
    float sq = 0.f;
#pragma unroll
    for (int i = lane; i < SLOTS; i += 32) sq += sr[i];
#pragma unroll
    for (int o = 16; o > 0; o >>= 1) sq += __shfl_xor_sync(0xFFFFFFFFu, sq, o);

    if (lane == 0) {
        g_pos[row]   = p * INV_T;
        g_sqrow[row] = sq;
    }
}

// ================= kernel 3: final loss (tiny) =================
__global__ void final_kernel(float* __restrict__ out) {
    __shared__ float sh[R];
    int t = threadIdx.x;          // 512
    float pos = g_pos[t];
    float sq  = g_sqrow[t];
    sh[t] = ex2f(pos * LOG2E);
    __syncthreads();
    for (int off = 128; off > 0; off >>= 1) {
        if ((t & 255) < off) sh[t] += sh[t + off];
        __syncthreads();
    }
    float spos = sh[(t >> 8) << 8];
    __syncthreads();
    sh[t] = pos - logf(spos + sq);
    __syncthreads();
    for (int off = 256; off > 0; off >>= 1) {
        if (t < off) sh[t] += sh[t + off];
        __syncthreads();
    }
    if (t == 0) out[0] = -sh[0] / (float)B;
}

// ================= launch =================
extern "C" void kernel_launch(void* const* d_in, const int* in_sizes, int n_in,
                              void* d_out, int out_size) {
    (void)in_sizes; (void)n_in; (void)out_size;
    const float* V     = (const float*)d_in[0];
    const float* L     = (const float*)d_in[1];
    const float* queue = (const float*)d_in[2];
    float* out = (float*)d_out;

    cudaFuncSetAttribute(gemm_exp_kernel, cudaFuncAttributeMaxDynamicSharedMemorySize, SMEM_BYTES);

    gemm_exp_kernel<<<SLOTS, 512, SMEM_BYTES>>>(V, queue);
    reduce_kernel<<<64, 256>>>(V, L);
    final_kernel<<<1, 512>>>(out);
}

// round 16
// speedup vs baseline: 1.1145x; 1.0120x over previous
#include <cuda_runtime.h>
#include <cuda_bf16.h>
#include <cstdint>

#define DEVINL __device__ __forceinline__

// ---------------- problem constants ----------------
constexpr int F  = 128;      // feature dim (K)
constexpr int B  = 256;      // batch
constexpr int R  = 512;      // J*B GEMM rows
constexpr int Q  = 65536;    // queue size
constexpr int TN = 64;       // queue rows per chunk
constexpr int QG = Q / TN;   // 1024 chunks
constexpr int SLOTS = 148;   // persistent CTAs (1 per SM)
constexpr int SSTR = 272;    // padded bf16 row stride in smem bytes
constexpr float INV_T = 10.0f;
constexpr float LOG2E = 1.4426950408889634f;
constexpr float CEXP  = INV_T * LOG2E;   // exp(10*d) = 2^(CEXP*d); folded into A

constexpr int F32_BUF  = TN * F * 4;     // 32768 raw fp32 chunk
constexpr int BF_BUF   = TN * SSTR;      // 17408 padded bf16 tile
// smem: [3 x fp32 stage (mod-3)][4 x bf16 tile (mod-4)]
constexpr int SMEM_BYTES = 3 * F32_BUF + 4 * BF_BUF;   // 167936

// ---------------- scratch (no allocs allowed) ----------------
__device__ float g_sq[R * SLOTS];        // [row][slot] partials
__device__ float g_pos[R];
__device__ float g_sqrow[R];

// ---------------- helpers ----------------
DEVINL float ex2f(float x) { float y; asm("ex2.approx.ftz.f32 %0, %1;" : "=f"(y) : "f"(x)); return y; }

DEVINL uint32_t cvt2(float a, float b) {
    __nv_bfloat162 h = __floats2bfloat162_rn(a, b);
    return *reinterpret_cast<uint32_t*>(&h);
}

DEVINL uint32_t smem_u32(const void* p) {
    uint32_t a;
    asm("{ .reg .u64 t; cvta.to.shared.u64 t, %1; cvt.u32.u64 %0, t; }" : "=r"(a) : "l"(p));
    return a;
}

DEVINL void mma16816(float* d, const uint32_t* a, uint32_t b0, uint32_t b1) {
    asm volatile(
        "mma.sync.aligned.m16n8k16.row.col.f32.bf16.bf16.f32 "
        "{%0,%1,%2,%3}, {%4,%5,%6,%7}, {%8,%9}, {%0,%1,%2,%3};"
        : "+f"(d[0]), "+f"(d[1]), "+f"(d[2]), "+f"(d[3])
        : "r"(a[0]), "r"(a[1]), "r"(a[2]), "r"(a[3]), "r"(b0), "r"(b1));
}

DEVINL void ldsm_x4(uint32_t* r, uint32_t addr) {
    asm volatile("ldmatrix.sync.aligned.m8n8.x4.shared.b16 {%0,%1,%2,%3}, [%4];"
                 : "=r"(r[0]), "=r"(r[1]), "=r"(r[2]), "=r"(r[3]) : "r"(addr));
}

DEVINL void cp16(uint32_t smem_dst, const void* gsrc) {
    asm volatile("cp.async.cg.shared.global [%0], [%1], 16;" :: "r"(smem_dst), "l"(gsrc));
}
DEVINL void cp_commit() { asm volatile("cp.async.commit_group;" ::: "memory"); }
DEVINL void cp_wait1()  { asm volatile("cp.async.wait_group 1;" ::: "memory"); }
DEVINL void cp_wait2()  { asm volatile("cp.async.wait_group 2;" ::: "memory"); }

// ================= kernel 1: persistent HMMA GEMM, barrier every OTHER chunk =================
// grid = SLOTS. CTA slot: all 512 rows x chunks qg = slot, slot+SLOTS, ...
// 16 warps; warp w owns rows [w*32, w*32+32). Tiles mod-4, fp32 staging mod-3.
__global__ void __launch_bounds__(512, 1)
gemm_exp_kernel(const float* __restrict__ V, const float* __restrict__ queue) {
    extern __shared__ char smem[];
    const uint32_t sb   = smem_u32(smem);
    const uint32_t bf_b = sb + 3 * F32_BUF;

    const int tid  = threadIdx.x;                // 0..511
    const int w    = tid >> 5;                   // 0..15 -> rows w*32..+31
    const int lane = tid & 31;
    const int g    = lane >> 2;
    const int tg   = lane & 3;
    const int slot = blockIdx.x;                 // 0..147

    // ---- A fragments: fp32 V -> bf16 regs, pre-scaled by CEXP (64 regs) ----
    uint32_t a[2][8][4];
    {
        const float* Ab = V + (size_t)(w * 32) * F;
#pragma unroll
        for (int m = 0; m < 2; m++)
#pragma unroll
            for (int k = 0; k < 8; k++) {
                int r0 = m * 16 + g, r1 = r0 + 8;
                int c0 = k * 16 + 2 * tg, c1 = c0 + 8;
                float2 f;
                f = *(const float2*)(Ab + r0 * F + c0); a[m][k][0] = cvt2(f.x * CEXP, f.y * CEXP);
                f = *(const float2*)(Ab + r1 * F + c0); a[m][k][1] = cvt2(f.x * CEXP, f.y * CEXP);
                f = *(const float2*)(Ab + r0 * F + c1); a[m][k][2] = cvt2(f.x * CEXP, f.y * CEXP);
                f = *(const float2*)(Ab + r1 * F + c1); a[m][k][3] = cvt2(f.x * CEXP, f.y * CEXP);
            }
    }

    // fp32 staging: 64 rows x 512B; each thread 4 x 16B. Chunk k -> fp32 buf k%3.
    const int srow = tid >> 3;
    const int sseg = (tid & 7) * 64;
    auto stage = [&](int buf3, int qg) {
        const char* src = (const char*)(queue + (size_t)qg * TN * F) + srow * 512 + sseg;
        uint32_t dst = sb + buf3 * F32_BUF + srow * 512 + sseg;
#pragma unroll
        for (int j = 0; j < 4; j++) cp16(dst + j * 16, src + j * 16);
    };

    // convert one quarter (512 float4) of fp32 buf (k%3) -> bf16 tile (k&3)
    auto convert_q = [&](int buf3, int buf4, int quarter) {
        int idx = quarter * 512 + tid;           // 0..2047
        int row = idx >> 5, c4 = idx & 31;
        float4 v4 = *((const float4*)(smem + buf3 * F32_BUF) + idx);
        uint2 o; o.x = cvt2(v4.x, v4.y); o.y = cvt2(v4.z, v4.w);
        *reinterpret_cast<uint2*>(smem + 3 * F32_BUF + buf4 * BF_BUF + row * SSTR + c4 * 8) = o;
    };

    const int nch = (QG - slot + SLOTS - 1) / SLOTS;   // 6 or 7 (always >= 6)

    float s00 = 0.f, s01 = 0.f, s10 = 0.f, s11 = 0.f;

    // ---- prologue: stage chunks 0,1,2; convert chunks 0,1 ----
    stage(0, slot);             cp_commit();
    stage(1, slot + SLOTS);     cp_commit();
    stage(2, slot + 2 * SLOTS); cp_commit();
    cp_wait2();                 // stage(0) done
#pragma unroll
    for (int q = 0; q < 4; q++) convert_q(0, 0, q);
    cp_wait1();                 // stage(1) done
#pragma unroll
    for (int q = 0; q < 4; q++) convert_q(1, 1, q);
    __syncthreads();            // tiles 0,1 visible; 1 group outstanding (stage(2))

    int qg = slot;
#pragma unroll 1
    for (int c = 0; c < nch; c++, qg += SLOTS) {
        if (c + 3 < nch) stage(c % 3, qg + 3 * SLOTS);   // chunk c+3 -> fp32 buf (c+3)%3 == c%3
        cp_commit();                                      // uniform group count

        const uint32_t lbase = bf_b + (c & 3) * BF_BUF + (lane & 7) * SSTR + (lane >> 3) * 16;
        const bool has_next = (c + 2 < nch);
        const int cb3 = (c + 2) % 3, cb4 = (c + 2) & 3;

        // software pipeline: bqp = kp0,kp1 fragments (prefetched); bqc = kp2,kp3 (in-iter)
        uint32_t bqp[8], bqc[8];
        ldsm_x4(bqp,     lbase);
        ldsm_x4(bqp + 4, lbase + 64);

        float u[8];
#pragma unroll
        for (int n8 = 0; n8 < 8; n8++) {
            if (n8 == 4) cp_wait1();                      // stage(c+2) landed
            if (n8 >= 4 && has_next) convert_q(cb3, cb4, n8 - 4);

            const uint32_t nb  = lbase + n8 * 8 * SSTR;
            const uint32_t nbn = lbase + ((n8 + 1) & 7) * 8 * SSTR;

            ldsm_x4(bqc,     nb + 128);
            ldsm_x4(bqc + 4, nb + 192);

            float x0[4] = {0,0,0,0}, x1[4] = {0,0,0,0};
            float y0[4] = {0,0,0,0}, y1[4] = {0,0,0,0};
            mma16816(x0, a[0][0], bqp[0], bqp[1]);
            mma16816(x0, a[0][1], bqp[2], bqp[3]);
            mma16816(y0, a[1][0], bqp[0], bqp[1]);
            mma16816(y0, a[1][1], bqp[2], bqp[3]);
            mma16816(x1, a[0][2], bqp[4], bqp[5]);
            mma16816(x1, a[0][3], bqp[6], bqp[7]);
            mma16816(y1, a[1][2], bqp[4], bqp[5]);
            mma16816(y1, a[1][3], bqp[6], bqp[7]);
            if (n8 < 7) {
                ldsm_x4(bqp,     nbn);
                ldsm_x4(bqp + 4, nbn + 64);
            }
            mma16816(x0, a[0][4], bqc[0], bqc[1]);
            mma16816(x0, a[0][5], bqc[2], bqc[3]);
            mma16816(y0, a[1][4], bqc[0], bqc[1]);
            mma16816(y0, a[1][5], bqc[2], bqc[3]);
            mma16816(x1, a[0][6], bqc[4], bqc[5]);
            mma16816(x1, a[0][7], bqc[6], bqc[7]);
            mma16816(y1, a[1][6], bqc[4], bqc[5]);
            mma16816(y1, a[1][7], bqc[6], bqc[7]);

            if (n8 > 0) {   // deferred ex2 of previous iteration overlaps this iter's mma
                s00 += ex2f(u[0]) + ex2f(u[1]);
                s01 += ex2f(u[2]) + ex2f(u[3]);
                s10 += ex2f(u[4]) + ex2f(u[5]);
                s11 += ex2f(u[6]) + ex2f(u[7]);
            }
#pragma unroll
            for (int i = 0; i < 4; i++) { u[i] = x0[i] + x1[i]; u[4 + i] = y0[i] + y1[i]; }
        }
        s00 += ex2f(u[0]) + ex2f(u[1]);
        s01 += ex2f(u[2]) + ex2f(u[3]);
        s10 += ex2f(u[4]) + ex2f(u[5]);
        s11 += ex2f(u[6]) + ex2f(u[7]);

        // barrier only after odd chunks: seals pair (c-1, c) reads before their tiles
        // and fp32 buffers are overwritten (mod-4 tiles / mod-3 staging give the slack).
        if (c & 1) __syncthreads();
    }

    // ---- quad reduce over tg, transposed deterministic store ----
    s00 += __shfl_xor_sync(0xFFFFFFFFu, s00, 1); s00 += __shfl_xor_sync(0xFFFFFFFFu, s00, 2);
    s01 += __shfl_xor_sync(0xFFFFFFFFu, s01, 1); s01 += __shfl_xor_sync(0xFFFFFFFFu, s01, 2);
    s10 += __shfl_xor_sync(0xFFFFFFFFu, s10, 1); s10 += __shfl_xor_sync(0xFFFFFFFFu, s10, 2);
    s11 += __shfl_xor_sync(0xFFFFFFFFu, s11, 1); s11 += __shfl_xor_sync(0xFFFFFFFFu, s11, 2);
    if (tg == 0) {
        int rb = w * 32;
        g_sq[(size_t)(rb + g)      * SLOTS + slot] = s00;
        g_sq[(size_t)(rb + g + 8)  * SLOTS + slot] = s01;
        g_sq[(size_t)(rb + g + 16) * SLOTS + slot] = s10;
        g_sq[(size_t)(rb + g + 24) * SLOTS + slot] = s11;
    }
}

// ================= kernel 2: per-row pos + slot reduction (64 CTAs, warp/row) =================
__global__ void __launch_bounds__(256) reduce_kernel(const float* __restrict__ V,
                                                     const float* __restrict__ L) {
    const int w    = threadIdx.x >> 5;
    const int lane = threadIdx.x & 31;
    const int row  = blockIdx.x * 8 + w;      // 64 CTAs x 8 warps = 512 rows

    float4 av = ((const float4*)(V + (size_t)row * F))[lane];
    float4 lv = ((const float4*)(L + (size_t)(row & (B - 1)) * F))[lane];
    float p = av.x * lv.x + av.y * lv.y + av.z * lv.z + av.w * lv.w;
#pragma unroll
    for (int o = 16; o > 0; o >>= 1) p += __shfl_xor_sync(0xFFFFFFFFu, p, o);

    const float* sr = g_sq + (size_t)row * SLOTS;
    float sq = 0.f;
#pragma unroll
    for (int i = lane; i < SLOTS; i += 32) sq += sr[i];
#pragma unroll
    for (int o = 16; o > 0; o >>= 1) sq += __shfl_xor_sync(0xFFFFFFFFu, sq, o);

    if (lane == 0) {
        g_pos[row]   = p * INV_T;
        g_sqrow[row] = sq;
    }
}

// ================= kernel 3: final loss (tiny) =================
__global__ void final_kernel(float* __restrict__ out) {
    __shared__ float sh[R];
    int t = threadIdx.x;          // 512
    float pos = g_pos[t];
    float sq  = g_sqrow[t];
    sh[t] = ex2f(pos * LOG2E);
    __syncthreads();
    for (int off = 128; off > 0; off >>= 1) {
        if ((t & 255) < off) sh[t] += sh[t + off];
        __syncthreads();
    }
    float spos = sh[(t >> 8) << 8];
    __syncthreads();
    sh[t] = pos - logf(spos + sq);
    __syncthreads();
    for (int off = 256; off > 0; off >>= 1) {
        if (t < off) sh[t] += sh[t + off];
        __syncthreads();
    }
    if (t == 0) out[0] = -sh[0] / (float)B;
}

// ================= launch =================
extern "C" void kernel_launch(void* const* d_in, const int* in_sizes, int n_in,
                              void* d_out, int out_size) {
    (void)in_sizes; (void)n_in; (void)out_size;
    const float* V     = (const float*)d_in[0];
    const float* L     = (const float*)d_in[1];
    const float* queue = (const float*)d_in[2];
    float* out = (float*)d_out;

    cudaFuncSetAttribute(gemm_exp_kernel, cudaFuncAttributeMaxDynamicSharedMemorySize, SMEM_BYTES);

    gemm_exp_kernel<<<SLOTS, 512, SMEM_BYTES>>>(V, queue);
    reduce_kernel<<<64, 256>>>(V, L);
    final_kernel<<<1, 512>>>(out);
}